// round 8
// baseline (speedup 1.0000x reference)
#include <cuda_runtime.h>
#include <cuda_fp16.h>
#include <math.h>

#define HIDDEN 64
#define MBATCH 32
#define ATOM   64
#define NUM_RBF 300

#define S_INT   512
#define TAB_ROWS 513                    // row s = h(s*H_STEP), s in [0,512]
#define H_STEP  (10.0f / 512.0f)
#define INV_H   51.2f

typedef unsigned long long u64;

// device scratch (no allocations allowed)
__device__ __align__(16) unsigned g_table_h[515 * 32];   // fp16x2 table, row=128B
__device__ __align__(16) float g_v1[MBATCH * ATOM * HIDDEN];
__device__ __align__(16) float g_pair[MBATCH * ATOM * HIDDEN];

__device__ __forceinline__ float softplus_f(float v) {
    return fmaxf(v, 0.0f) + log1pf(expf(-fabsf(v)));
}

// packed f32x2 helpers (Blackwell FFMA2 / FADD2)
__device__ __forceinline__ u64 fma2(u64 a, u64 b, u64 c) {
    u64 d; asm("fma.rn.f32x2 %0, %1, %2, %3;" : "=l"(d) : "l"(a), "l"(b), "l"(c)); return d;
}
__device__ __forceinline__ u64 add2(u64 a, u64 b) {
    u64 d; asm("add.rn.f32x2 %0, %1, %2;" : "=l"(d) : "l"(a), "l"(b)); return d;
}
__device__ __forceinline__ u64 pack2(float a, float b) {
    u64 d; asm("mov.b64 %0, {%1, %2};" : "=l"(d) : "f"(a), "f"(b)); return d;
}
__device__ __forceinline__ unsigned h2bits(float w) {
    __half2 h = __float2half2_rn(w);
    return *reinterpret_cast<unsigned*>(&h);
}
__device__ __forceinline__ __half2 bits2h(unsigned u) {
    return *reinterpret_cast<__half2*>(&u);
}

// ---------------------------------------------------------------------------
// Prep kernel, 512 threads/block:
//   blocks [0,65):    h(d) table (fp16), 8 samples/block
//   blocks [65,129):  v1 = x@W1^T + b1
// ---------------------------------------------------------------------------
#define TAB_BLOCKS 65
#define V1_BLOCKS  64
#define PREP_BLOCKS (TAB_BLOCKS + V1_BLOCKS)
#define PREP_SMEM ((64*301 + 64*65 + 8*304 + 8*64) * 4)

__global__ void __launch_bounds__(512) prep_kernel(
    const float* __restrict__ x,  const float* __restrict__ W1, const float* __restrict__ b1,
    const float* __restrict__ Wd1, const float* __restrict__ bd1,
    const float* __restrict__ Wd2, const float* __restrict__ bd2)
{
    extern __shared__ float sh[];
    const int tid = threadIdx.x;
    const int b = blockIdx.x;

    if (b < TAB_BLOCKS) {
        float* Wd1_s = sh;                   // 64 x 301 (padded)
        float* Wd2_s = Wd1_s + 64 * 301;     // 64 x 65
        float* rbf_s = Wd2_s + 64 * 65;      // 8 x 304
        float* g_s   = rbf_s + 8 * 304;      // 8 x 64

        for (int idx = tid; idx < 64 * NUM_RBF; idx += 512) {
            int cc = idx / NUM_RBF;
            int r  = idx - cc * NUM_RBF;
            Wd1_s[cc * 301 + r] = Wd1[idx];
        }
        for (int idx = tid; idx < 4096; idx += 512)
            Wd2_s[(idx >> 6) * 65 + (idx & 63)] = Wd2[idx];
        const int s0 = b * 8;
        for (int idx = tid; idx < 8 * NUM_RBF; idx += 512) {
            int qq = idx / NUM_RBF;
            int r  = idx - qq * NUM_RBF;
            float dd = (float)(s0 + qq) * H_STEP;
            float u = dd - 0.1f * (float)r;
            rbf_s[qq * 304 + r] = __expf(-10.0f * u * u);
        }
        __syncthreads();

        const int q = tid >> 6;
        const int c = tid & 63;
        const int s = s0 + q;
        const float d = (float)s * H_STEP;
        int rlo = (int)ceilf((d - 1.5f) * 10.0f); if (rlo < 0) rlo = 0;
        int rhi = (int)floorf((d + 1.5f) * 10.0f); if (rhi > NUM_RBF - 1) rhi = NUM_RBF - 1;
        float p = bd1[c];
        const float* wrow = Wd1_s + c * 301;
        const float* rrow = rbf_s + q * 304;
        for (int r = rlo; r <= rhi; r++) p = fmaf(wrow[r], rrow[r], p);
        g_s[q * 64 + c] = softplus_f(p);
        __syncthreads();

        float qv = bd2[c];
        const float* w2row = Wd2_s + c * 65;
        const float* gg = g_s + q * 64;
        #pragma unroll 8
        for (int k = 0; k < 64; k++) qv = fmaf(w2row[k], gg[k], qv);
        if (s < TAB_ROWS)
            ((__half*)g_table_h)[s * 64 + c] = __float2half_rn(softplus_f(qv));
    } else {
        const int v = b - TAB_BLOCKS;
        const int m = v >> 1, half = v & 1;
        float* W1p = sh;                 // 64 x 68 padded
        float* xp  = sh + 64 * 68;       // 32 x 68

        for (int idx = tid; idx < 4096; idx += 512)
            W1p[(idx >> 6) * 68 + (idx & 63)] = W1[idx];
        for (int idx = tid; idx < 2048; idx += 512)
            xp[(idx >> 6) * 68 + (idx & 63)] = x[m * 4096 + (half * 32 + (idx >> 6)) * 64 + (idx & 63)];
        __syncthreads();

        const int ii = tid & 31;
        const int oh = tid >> 5;
        float4 acc = make_float4(0.f, 0.f, 0.f, 0.f);
        const float* xr = xp + ii * 68;
        const float* wr = W1p + oh * 4 * 68;
        #pragma unroll
        for (int c4 = 0; c4 < 16; c4++) {
            float4 xv = *(const float4*)(xr + c4 * 4);
            float4 w0 = *(const float4*)(wr + 0 * 68 + c4 * 4);
            float4 w1 = *(const float4*)(wr + 1 * 68 + c4 * 4);
            float4 w2 = *(const float4*)(wr + 2 * 68 + c4 * 4);
            float4 w3 = *(const float4*)(wr + 3 * 68 + c4 * 4);
            acc.x = fmaf(xv.x, w0.x, fmaf(xv.y, w0.y, fmaf(xv.z, w0.z, fmaf(xv.w, w0.w, acc.x))));
            acc.y = fmaf(xv.x, w1.x, fmaf(xv.y, w1.y, fmaf(xv.z, w1.z, fmaf(xv.w, w1.w, acc.y))));
            acc.z = fmaf(xv.x, w2.x, fmaf(xv.y, w2.y, fmaf(xv.z, w2.z, fmaf(xv.w, w2.w, acc.z))));
            acc.w = fmaf(xv.x, w3.x, fmaf(xv.y, w3.y, fmaf(xv.z, w3.z, fmaf(xv.w, w3.w, acc.w))));
        }
        float4 bv = *(const float4*)(b1 + oh * 4);
        acc.x += bv.x; acc.y += bv.y; acc.z += bv.z; acc.w += bv.w;
        *(float4*)(g_v1 + (m * 64 + half * 32 + ii) * 64 + oh * 4) = acc;
    }
}

// ---------------------------------------------------------------------------
// Main kernel: 256 blocks = (m, j-group of 8), 512 threads (16 warps),
// 2 CTAs/SM. Warp = (ihalf, jj); lane = channel pair; 2 independent
// i-chains (ILP=2). v1 read via LDG from L2. Writes PAIR to g_pair.
// ---------------------------------------------------------------------------
// smem: TAB 16480 u32 | W4 2048 f | PART 1024 f = 19552*4 = 78208 B
#define MAIN_SMEM (19552 * 4)

__global__ void __launch_bounds__(512, 2) main_kernel(
    const float* __restrict__ dist)
{
    extern __shared__ float sh[];
    unsigned* TABu = (unsigned*)sh;       // 16480
    float* W4s  = sh + 16480;             // 2048 : per-pair (wm,w0,wp h2-bits, koff)
    float* PARTs= W4s + 2048;             // 1024 : 2-way u64 partials

    const int tid = threadIdx.x;
    const int m  = blockIdx.x >> 3;
    const int j0 = (blockIdx.x & 7) << 3;

    // stage fp16 table (64.4KB)
    {
        const uint4* ts = (const uint4*)g_table_h;
        uint4* td = (uint4*)TABu;
        #pragma unroll
        for (int r = 0; r < 8; r++) td[tid + r * 512] = ts[tid + r * 512];
        if (tid < 24) td[4096 + tid] = ts[4096 + tid];
    }
    // per-pair quadratic weights around nearest node k (nodes k-1,k,k+1)
    {
        const int p = tid;                 // 512 pairs: (i, jj)
        const int i = p >> 3, jj = p & 7;
        float d = dist[(m * 64 + i) * 64 + j0 + jj];
        float t = d * INV_H;
        int k = __float2int_rn(t);
        k = min(max(k, 1), S_INT - 1);
        float u = t - (float)k;
        float wm = 0.5f * u * (u - 1.0f);
        float w0 = 1.0f - u * u;
        float wp = 0.5f * u * (u + 1.0f);
        float4 wk;
        wk.x = __uint_as_float(h2bits(wm));
        wk.y = __uint_as_float(h2bits(w0));
        wk.z = __uint_as_float(h2bits(wp));
        wk.w = __int_as_float((k - 1) << 7);   // byte offset of first tap row
        ((float4*)W4s)[p] = wk;
    }
    __syncthreads();

    const int warp  = tid >> 5;
    const int jj    = warp & 7;      // destination atom within group
    const int ihalf = warp >> 3;     // 0..1 : i-range half
    const int t     = tid & 31;      // lane = channel pair (2t, 2t+1)

    u64 acc_a = 0ull, acc_b = 0ull;
    const char* tb = (const char*)TABu + (t << 2);
    const u64* v1g = (const u64*)g_v1 + m * 2048 + t;   // + i*32 per row
    const float4* W4v = ((const float4*)W4s) + jj;
    const int ibase = ihalf << 5;

    #pragma unroll 4
    for (int ii = 0; ii < 16; ii++) {
        const int ia = ibase + ii;
        const int ib = ibase + 16 + ii;
        float4 wka = W4v[ia << 3];
        float4 wkb = W4v[ib << 3];
        int ka = __float_as_int(wka.w);
        int kb = __float_as_int(wkb.w);
        unsigned a0 = *(const unsigned*)(tb + ka);
        unsigned a1 = *(const unsigned*)(tb + ka + 128);
        unsigned a2 = *(const unsigned*)(tb + ka + 256);
        unsigned b0 = *(const unsigned*)(tb + kb);
        unsigned b1v = *(const unsigned*)(tb + kb + 128);
        unsigned b2v = *(const unsigned*)(tb + kb + 256);
        u64 vva = v1g[ia << 5];
        u64 vvb = v1g[ib << 5];
        __half2 ha = __hfma2(bits2h(__float_as_uint(wka.x)), bits2h(a0),
                     __hfma2(bits2h(__float_as_uint(wka.y)), bits2h(a1),
                     __hmul2(bits2h(__float_as_uint(wka.z)), bits2h(a2))));
        __half2 hb = __hfma2(bits2h(__float_as_uint(wkb.x)), bits2h(b0),
                     __hfma2(bits2h(__float_as_uint(wkb.y)), bits2h(b1v),
                     __hmul2(bits2h(__float_as_uint(wkb.z)), bits2h(b2v))));
        float2 fa = __half22float2(ha);
        float2 fb = __half22float2(hb);
        acc_a = fma2(vva, pack2(fa.x, fa.y), acc_a);
        acc_b = fma2(vvb, pack2(fb.x, fb.y), acc_b);
    }
    ((u64*)PARTs)[(ihalf << 8) + (jj << 5) + t] = add2(acc_a, acc_b);
    __syncthreads();

    // reduce across ihalf and write PAIR rows to global
    if (tid < 256) {
        const u64* pp = (const u64*)PARTs;
        u64 a = add2(pp[tid], pp[tid + 256]);
        const int g = tid >> 5;          // j-row within group
        ((u64*)g_pair)[(m * 64 + j0 + g) * 32 + (tid & 31)] = a;
    }
}

// ---------------------------------------------------------------------------
// Epilogue kernel: 64 blocks x 512 threads, 32 rows each.
// out = x + W3 @ softplus(W2 @ pair + b2) + b3  (row-wise)
// ---------------------------------------------------------------------------
#define EPI_SMEM ((64*68 + 64*68 + 32*68 + 32*68) * 4)   // 52224 B

__global__ void __launch_bounds__(512) epi_kernel(
    const float* __restrict__ x,
    const float* __restrict__ W2, const float* __restrict__ b2,
    const float* __restrict__ W3, const float* __restrict__ b3,
    float* __restrict__ out)
{
    extern __shared__ float sh[];
    float* W2p = sh;                 // 64 x 68
    float* W3p = W2p + 64 * 68;      // 64 x 68
    float* Pp  = W3p + 64 * 68;      // 32 x 68
    float* V2p = Pp + 32 * 68;       // 32 x 68

    const int tid = threadIdx.x;
    const int row0 = blockIdx.x * 32;

    for (int idx = tid; idx < 4096; idx += 512) {
        int o = idx >> 6, c = idx & 63;
        W2p[o * 68 + c] = W2[idx];
        W3p[o * 68 + c] = W3[idx];
    }
    for (int idx = tid; idx < 2048; idx += 512)
        Pp[(idx >> 6) * 68 + (idx & 63)] = g_pair[row0 * 64 + idx];
    __syncthreads();

    const int ii = tid & 31;         // row within block
    const int oh = tid >> 5;         // output quad 0..15

    // layer 2: softplus(P @ W2^T + b2)
    {
        float4 acc = make_float4(0.f, 0.f, 0.f, 0.f);
        const float* xr = Pp + ii * 68;
        const float* wr = W2p + oh * 4 * 68;
        #pragma unroll
        for (int c4 = 0; c4 < 16; c4++) {
            float4 xv = *(const float4*)(xr + c4 * 4);
            float4 w0 = *(const float4*)(wr + 0 * 68 + c4 * 4);
            float4 w1 = *(const float4*)(wr + 1 * 68 + c4 * 4);
            float4 w2 = *(const float4*)(wr + 2 * 68 + c4 * 4);
            float4 w3 = *(const float4*)(wr + 3 * 68 + c4 * 4);
            acc.x = fmaf(xv.x, w0.x, fmaf(xv.y, w0.y, fmaf(xv.z, w0.z, fmaf(xv.w, w0.w, acc.x))));
            acc.y = fmaf(xv.x, w1.x, fmaf(xv.y, w1.y, fmaf(xv.z, w1.z, fmaf(xv.w, w1.w, acc.y))));
            acc.z = fmaf(xv.x, w2.x, fmaf(xv.y, w2.y, fmaf(xv.z, w2.z, fmaf(xv.w, w2.w, acc.z))));
            acc.w = fmaf(xv.x, w3.x, fmaf(xv.y, w3.y, fmaf(xv.z, w3.z, fmaf(xv.w, w3.w, acc.w))));
        }
        float4 bv = *(const float4*)(b2 + oh * 4);
        acc.x = softplus_f(acc.x + bv.x);
        acc.y = softplus_f(acc.y + bv.y);
        acc.z = softplus_f(acc.z + bv.z);
        acc.w = softplus_f(acc.w + bv.w);
        *(float4*)(V2p + ii * 68 + oh * 4) = acc;
    }
    __syncthreads();

    // layer 3 + residual
    {
        float4 acc = make_float4(0.f, 0.f, 0.f, 0.f);
        const float* xr = V2p + ii * 68;
        const float* wr = W3p + oh * 4 * 68;
        #pragma unroll
        for (int c4 = 0; c4 < 16; c4++) {
            float4 xv = *(const float4*)(xr + c4 * 4);
            float4 w0 = *(const float4*)(wr + 0 * 68 + c4 * 4);
            float4 w1 = *(const float4*)(wr + 1 * 68 + c4 * 4);
            float4 w2 = *(const float4*)(wr + 2 * 68 + c4 * 4);
            float4 w3 = *(const float4*)(wr + 3 * 68 + c4 * 4);
            acc.x = fmaf(xv.x, w0.x, fmaf(xv.y, w0.y, fmaf(xv.z, w0.z, fmaf(xv.w, w0.w, acc.x))));
            acc.y = fmaf(xv.x, w1.x, fmaf(xv.y, w1.y, fmaf(xv.z, w1.z, fmaf(xv.w, w1.w, acc.y))));
            acc.z = fmaf(xv.x, w2.x, fmaf(xv.y, w2.y, fmaf(xv.z, w2.z, fmaf(xv.w, w2.w, acc.z))));
            acc.w = fmaf(xv.x, w3.x, fmaf(xv.y, w3.y, fmaf(xv.z, w3.z, fmaf(xv.w, w3.w, acc.w))));
        }
        float4 bv = *(const float4*)(b3 + oh * 4);
        const int gidx = (row0 + ii) * 64 + oh * 4;
        float4 xv = *(const float4*)(x + gidx);
        acc.x += bv.x + xv.x;
        acc.y += bv.y + xv.y;
        acc.z += bv.z + xv.z;
        acc.w += bv.w + xv.w;
        *(float4*)(out + gidx) = acc;
    }
}

extern "C" void kernel_launch(void* const* d_in, const int* in_sizes, int n_in,
                              void* d_out, int out_size) {
    const float* x   = (const float*)d_in[0];
    const float* dist= (const float*)d_in[1];
    const float* W1  = (const float*)d_in[2];
    const float* b1  = (const float*)d_in[3];
    const float* W2  = (const float*)d_in[4];
    const float* b2  = (const float*)d_in[5];
    const float* W3  = (const float*)d_in[6];
    const float* b3  = (const float*)d_in[7];
    const float* Wd1 = (const float*)d_in[8];
    const float* bd1 = (const float*)d_in[9];
    const float* Wd2 = (const float*)d_in[10];
    const float* bd2 = (const float*)d_in[11];
    float* out = (float*)d_out;
    (void)in_sizes; (void)n_in; (void)out_size;

    cudaFuncSetAttribute(prep_kernel, cudaFuncAttributeMaxDynamicSharedMemorySize, PREP_SMEM);
    cudaFuncSetAttribute(main_kernel, cudaFuncAttributeMaxDynamicSharedMemorySize, MAIN_SMEM);
    cudaFuncSetAttribute(epi_kernel,  cudaFuncAttributeMaxDynamicSharedMemorySize, EPI_SMEM);

    prep_kernel<<<PREP_BLOCKS, 512, PREP_SMEM>>>(x, W1, b1, Wd1, bd1, Wd2, bd2);
    main_kernel<<<256, 512, MAIN_SMEM>>>(dist);
    epi_kernel<<<64, 512, EPI_SMEM>>>(x, W2, b2, W3, b3, out);
}